// round 9
// baseline (speedup 1.0000x reference)
#include <cuda_runtime.h>
#include <cuda_fp16.h>
#include <math.h>
#include <stdint.h>

#define N_NODES 40000
#define N_PAD   40064          // 313 * 128
#define N_EDGES 640000
#define CCH 128
#define NQKV 384
#define M_TILES 313
#define QKV_GBLKS 939          // 3 col-tiles x 313 m-tiles
#define EDGE_BLKS 5000         // 8 nodes per block
#define FUSED_BLKS (QKV_GBLKS + EDGE_BLKS)

// prep_all block ranges
#define CSRB   592
#define CHUNK  68              // ceil(40000/592)
#define ZB     1
#define BIASB  3
#define CVTB   10016           // N_PAD*64 / 256 exact
#define PREPB  544             // 139264 / 256
#define PREP_BLKS (CSRB + ZB + BIASB + CVTB + PREPB)

// ---------------- device scratch ----------------
__device__ __half g_a16[(size_t)N_PAD * CCH];
__device__ __half g_qkv16[(size_t)N_PAD * NQKV];
__device__ __half g_agg16[(size_t)N_PAD * CCH];    // rows >=40000 stay zero
__device__ float  g_h1[(size_t)N_NODES * CCH];
__device__ int    g_rowptr[N_NODES + 1];
__device__ int    g_colsrc[N_EDGES];
__device__ int    g_counts[N_NODES];
__device__ int    g_fill[N_NODES];
__device__ int    g_bsums[CSRB];
__device__ float  g_bqkv[2 * NQKV];
__device__ __half g_bt[139264];
__device__ int    g_use64;
__device__ int    g_qkvcnt[2 * M_TILES];
__device__ int    g_qkvall[2];
__device__ int    g_bcnt;
__device__ volatile int g_bsense;

// ---------------- helpers ----------------
__device__ __forceinline__ uint32_t smem_u32(const void* p) {
    uint32_t a;
    asm("{ .reg .u64 t; cvta.to.shared.u64 t, %1; cvt.u32.u64 %0, t; }" : "=r"(a) : "l"(p));
    return a;
}
__device__ __forceinline__ void cp_async16(uint32_t dst, const void* src) {
    asm volatile("cp.async.ca.shared.global [%0], [%1], 16;" :: "r"(dst), "l"(src));
}
__device__ __forceinline__ void cp_async_wait_all() {
    asm volatile("cp.async.commit_group;");
    asm volatile("cp.async.wait_group 0;");
}
__device__ __forceinline__ int ld_idx(const void* ei, long long pos, int use64) {
    if (use64) return (int)((const long long*)ei)[pos];
    return ((const int*)ei)[pos];
}
__device__ __forceinline__ float gelu_tanh(float x) {
    float x3 = x * x * x;
    return 0.5f * x * (1.0f + tanhf(0.7978845608028654f * (x + 0.044715f * x3)));
}
__device__ __forceinline__ void ldsm4(uint32_t* r, uint32_t addr) {
    asm volatile("ldmatrix.sync.aligned.m8n8.x4.shared.b16 {%0,%1,%2,%3}, [%4];"
        : "=r"(r[0]), "=r"(r[1]), "=r"(r[2]), "=r"(r[3]) : "r"(addr));
}
__device__ __forceinline__ void mma16816(float* c, const uint32_t* a, uint32_t b0, uint32_t b1) {
    asm volatile("mma.sync.aligned.m16n8k16.row.col.f32.f16.f16.f32 "
        "{%0,%1,%2,%3}, {%4,%5,%6,%7}, {%8,%9}, {%0,%1,%2,%3};"
        : "+f"(c[0]), "+f"(c[1]), "+f"(c[2]), "+f"(c[3])
        : "r"(a[0]), "r"(a[1]), "r"(a[2]), "r"(a[3]), "r"(b0), "r"(b1));
}

// ---------------- prep_all: CSR(persistent) | zero-flags | bias | cvt_x | prep_b ----------------
__global__ __launch_bounds__(256, 4)
void prep_all(const float* __restrict__ x, const void* ei,
              const float* Wk, const float* bk, const float* Wq, const float* bq,
              const float* Wv, const float* bv,
              const float* a_rel, const float* m_rel, const float* p_rel,
              const float* aW, const float* fcW) {
    int b = blockIdx.x, tid = threadIdx.x;

    if (b < CSRB) {
        __shared__ int lsense;
        __shared__ int sh[256];
        __shared__ int any;
        if (tid == 0) lsense = g_bsense;   // entry sense (replay-safe)
        __syncthreads();
        auto gbar = [&]() {
            __threadfence();
            __syncthreads();
            if (tid == 0) {
                int ns = lsense ^ 1;
                lsense = ns;
                if (atomicAdd(&g_bcnt, 1) == CSRB - 1) {
                    g_bcnt = 0;
                    __threadfence();
                    g_bsense = ns;
                } else {
                    while (g_bsense != ns) __nanosleep(64);
                }
            }
            __syncthreads();
        };
        // P0: zero counts/fill + dtype detect
        int gid = b * 256 + tid;
        if (gid < N_NODES) { g_counts[gid] = 0; g_fill[gid] = 0; }
        if (b == 0) {
            if (tid == 0) any = 0;
            __syncthreads();
            int v = 0;
            const int* w = (const int*)ei;
            for (int i = tid; i < 2048; i += 256) v |= w[2 * i + 1];
            if (v) atomicOr(&any, 1);
            __syncthreads();
            if (tid == 0) g_use64 = (any == 0) ? 1 : 0;
        }
        gbar();
        int use64 = *(volatile int*)&g_use64;
        // P1: histogram
        for (int e = b * 256 + tid; e < N_EDGES; e += CSRB * 256)
            atomicAdd(&g_counts[ld_idx(ei, (long long)N_EDGES + e, use64)], 1);
        gbar();
        // P2: per-chunk exclusive scan
        int start = b * CHUNK;
        int n = N_NODES - start; if (n > CHUNK) n = CHUNK; if (n < 0) n = 0;
        int v2 = (tid < n) ? __ldcg(&g_counts[start + tid]) : 0;
        sh[tid] = v2; __syncthreads();
        #pragma unroll
        for (int o = 1; o < 256; o <<= 1) {
            int t = (tid >= o) ? sh[tid - o] : 0;
            __syncthreads(); sh[tid] += t; __syncthreads();
        }
        if (tid < n) g_rowptr[start + tid] = sh[tid] - v2;
        if (tid == 255) g_bsums[b] = sh[255];
        gbar();
        // P3: block 0 scans the block sums
        if (b == 0 && tid < 32) {
            int carry = 0;
            for (int base = 0; base < CSRB; base += 32) {
                int idx = base + tid;
                int v = (idx < CSRB) ? __ldcg(&g_bsums[idx]) : 0;
                int xx = v;
                #pragma unroll
                for (int o = 1; o < 32; o <<= 1) {
                    int t = __shfl_up_sync(0xffffffffu, xx, o);
                    if (tid >= o) xx += t;
                }
                if (idx < CSRB) g_bsums[idx] = carry + xx - v;
                carry += __shfl_sync(0xffffffffu, xx, 31);
            }
            if (tid == 0) g_rowptr[N_NODES] = carry;
        }
        gbar();
        // P4: add block offsets
        if (tid < n) {
            int off = __ldcg(&g_bsums[b]);
            g_rowptr[start + tid] = __ldcg(&g_rowptr[start + tid]) + off;
        }
        gbar();
        // P5: scatter
        for (int e = b * 256 + tid; e < N_EDGES; e += CSRB * 256) {
            int d = ld_idx(ei, (long long)N_EDGES + e, use64);
            int s = ld_idx(ei, e, use64);
            int pos = __ldcg(&g_rowptr[d]) + atomicAdd(&g_fill[d], 1);
            g_colsrc[pos] = s;
        }
        return;
    }
    b -= CSRB;
    if (b < ZB) {   // zero per-layer gemm flags
        for (int i = tid; i < 2 * M_TILES; i += 256) g_qkvcnt[i] = 0;
        if (tid < 2) g_qkvall[tid] = 0;
        return;
    }
    b -= ZB;
    if (b < BIASB) {   // fused QKV bias
        int idx = b * 256 + tid;
        if (idx < 768) {
            int l = idx / NQKV, c = idx % NQKV;
            int t = c >> 7, cc = c & 127, h = cc >> 4, eo = cc & 15;
            float bias;
            if (t == 0) bias = bq[l * 128 + cc] * p_rel[l * 8 + h] * 0.25f;
            else {
                const float* bm = (t == 1) ? bk : bv;
                const float* R  = (t == 1) ? a_rel : m_rel;
                float sb = 0.f;
                #pragma unroll
                for (int d = 0; d < 16; ++d)
                    sb += bm[l * 128 + h * 16 + d] * R[((l * 8 + h) * 16 + d) * 16 + eo];
                bias = sb;
            }
            g_bqkv[l * NQKV + c] = bias;
        }
        return;
    }
    b -= BIASB;
    if (b < CVTB) {   // x -> fp16 (+ zero padding rows)
        int i = b * 256 + tid;            // < N_PAD*64
        if (i < N_NODES * 64) {
            float2 v = ((const float2*)x)[i];
            ((__half2*)g_a16)[i] = __floats2half2_rn(v.x, v.y);
        } else {
            ((__half2*)g_a16)[i] = __floats2half2_rn(0.f, 0.f);
        }
        return;
    }
    b -= CVTB;
    {   // prep_b: fused-direct weight transform -> fp16 [tile][n][k]
        int e = b * 256 + tid;            // < 139264
        float val;
        if (e < 131072) {
            int tile = e >> 14, within = e & 16383;
            int nn = within >> 7, k = within & 127;
            int l = tile >> 2, t = tile & 3;
            if (t == 0)      val = Wq[(size_t)l * 16384 + k * 128 + nn] * p_rel[l * 8 + (nn >> 4)] * 0.25f;
            else if (t == 3) val = aW[(size_t)l * 16384 + k * 128 + nn];
            else {
                const float* Wm = (t == 1) ? Wk : Wv;
                const float* R  = (t == 1) ? a_rel : m_rel;
                int h = nn >> 4, eo = nn & 15;
                float s = 0.f;
                #pragma unroll
                for (int d = 0; d < 16; ++d)
                    s += Wm[(size_t)l * 16384 + k * 128 + h * 16 + d] * R[((l * 8 + h) * 16 + d) * 16 + eo];
                val = s;
            }
        } else {
            int e2 = e - 131072;
            int nn = e2 >> 7, k = e2 & 127;
            val = fcW[k * 64 + nn];
        }
        g_bt[e] = __float2half(val);
    }
}

// ---------------- gemm core: CTA 128m x NTn, 8 warps, warp 32m x (NT/2)n ----------------
template<int NT>
__device__ __forceinline__ void gemm_core(char* sm,
    const __half* __restrict__ A16, const __half* __restrict__ btile,
    const float* __restrict__ bias,
    float* C32, int c32s, __half* C16, int c16s,
    int mode, const float* skip, const float* gate, int m0) {
    constexpr int NB2 = NT / 32;
    constexpr uint32_t BOFF = 128 * 272;
    uint32_t sbase = smem_u32(sm);
    int tid = threadIdx.x, wid = tid >> 5, lane = tid & 31;

    const __half* asrc = A16 + (size_t)m0 * 128;
    #pragma unroll
    for (int i = tid; i < 2048; i += 256) {
        int row = i >> 4, kc = i & 15;
        cp_async16(sbase + row * 272 + kc * 16, asrc + row * 128 + kc * 8);
    }
    #pragma unroll
    for (int i = tid; i < NT * 16; i += 256) {
        int row = i >> 4, kc = i & 15;
        cp_async16(sbase + BOFF + row * 272 + kc * 16, btile + row * 128 + kc * 8);
    }
    cp_async_wait_all();
    __syncthreads();

    int wm = wid & 3, wn = wid >> 2;
    uint32_t arowoff[2];
    #pragma unroll
    for (int mb = 0; mb < 2; ++mb) {
        int arow = wm * 32 + mb * 16 + (lane & 15);
        arowoff[mb] = (uint32_t)arow * 272u + (uint32_t)(lane & 16);
    }
    uint32_t browoff[NB2];
    #pragma unroll
    for (int nb2 = 0; nb2 < NB2; ++nb2) {
        int brow = wn * (NT / 2) + nb2 * 16 + (lane & 7) + ((lane & 16) >> 1);
        browoff[nb2] = (uint32_t)brow * 272u + (uint32_t)((lane & 8) << 1);
    }

    float acc[2][2 * NB2][4];
    #pragma unroll
    for (int mb = 0; mb < 2; ++mb)
        #pragma unroll
        for (int nb = 0; nb < 2 * NB2; ++nb)
            #pragma unroll
            for (int j = 0; j < 4; ++j) acc[mb][nb][j] = 0.0f;

    #pragma unroll
    for (int ks = 0; ks < 8; ++ks) {
        uint32_t kb = (uint32_t)ks * 32u;
        uint32_t a[2][4];
        ldsm4(a[0], sbase + arowoff[0] + kb);
        ldsm4(a[1], sbase + arowoff[1] + kb);
        #pragma unroll
        for (int nb2 = 0; nb2 < NB2; ++nb2) {
            uint32_t bb[4];
            ldsm4(bb, sbase + BOFF + browoff[nb2] + kb);
            mma16816(acc[0][2 * nb2],     a[0], bb[0], bb[1]);
            mma16816(acc[1][2 * nb2],     a[1], bb[0], bb[1]);
            mma16816(acc[0][2 * nb2 + 1], a[0], bb[2], bb[3]);
            mma16816(acc[1][2 * nb2 + 1], a[1], bb[2], bb[3]);
        }
    }

    float beta = 0.f, ombeta = 0.f;
    if (mode == 1) {
        float g = gate[0];
        beta = 1.f / (1.f + expf(-g));
        ombeta = 1.f - beta;
    }
    int quad = lane >> 2, qt = lane & 3;
    int n0 = wn * (NT / 2);
    #pragma unroll
    for (int mb = 0; mb < 2; ++mb)
        #pragma unroll
        for (int half = 0; half < 2; ++half) {
            int grow = m0 + wm * 32 + mb * 16 + quad + half * 8;
            #pragma unroll
            for (int nb = 0; nb < 2 * NB2; ++nb) {
                int col = n0 + nb * 8 + qt * 2;
                float v0 = acc[mb][nb][2 * half + 0] + bias[col + 0];
                float v1 = acc[mb][nb][2 * half + 1] + bias[col + 1];
                if (mode == 1) {
                    float2 sv = make_float2(0.f, 0.f);
                    if (grow < N_NODES) sv = *(const float2*)(skip + (size_t)grow * 128 + col);
                    v0 = fmaxf(beta * v0 + ombeta * sv.x, 0.f);
                    v1 = fmaxf(beta * v1 + ombeta * sv.y, 0.f);
                }
                if (C32 && grow < N_NODES) {
                    float2 o; o.x = v0; o.y = v1;
                    *(float2*)(C32 + (size_t)grow * c32s + col) = o;
                }
                if (C16)
                    *(__half2*)(C16 + (size_t)grow * c16s + col) = __floats2half2_rn(v0, v1);
            }
        }
}

// ---------------- fused: QKV gemm blocks + edge blocks (flag-synced) ----------------
__global__ __launch_bounds__(256, 2)
void qkv_edge_kernel(int l) {
    extern __shared__ char sm[];
    if (blockIdx.x < QKV_GBLKS) {
        int bx = blockIdx.x % 3, by = blockIdx.x / 3;
        gemm_core<128>(sm, g_a16, g_bt + (size_t)(l * 4 + bx) * 16384,
                       g_bqkv + l * NQKV + bx * 128,
                       nullptr, 0, g_qkv16 + bx * 128, NQKV,
                       0, nullptr, nullptr, by * 128);
        __threadfence();
        __syncthreads();
        if (threadIdx.x == 0) {
            atomicAdd(&g_qkvcnt[l * M_TILES + by], 1);
            __threadfence();
            atomicAdd(&g_qkvall[l], 1);
        }
        return;
    }
    // ---- edge role: 8 warps = 8 dst nodes; 4 edges/iter, 8 lanes (1 head) per edge ----
    int eb = blockIdx.x - QKV_GBLKS;
    int tid = threadIdx.x, wid = tid >> 5, lane = tid & 31;
    int node = eb * 8 + wid;              // < 40000 exactly
    __shared__ int sfast;
    if (tid == 0) sfast = (*(volatile int*)&g_qkvall[l] == QKV_GBLKS) ? 1 : 0;
    __syncthreads();
    bool fast = sfast != 0;
    int sub = lane >> 3, j = lane & 7;    // j = head
    volatile int* cnt = (volatile int*)(g_qkvcnt + l * M_TILES);

    if (!fast) { int tq = node >> 7; while (cnt[tq] < 3) __nanosleep(64); }

    float q[16];
    {
        const uint4* qp = (const uint4*)(g_qkv16 + (size_t)node * NQKV + j * 16);
        uint4 q0 = qp[0], q1 = qp[1];
        const __half2* qh0 = (const __half2*)&q0;
        const __half2* qh1 = (const __half2*)&q1;
        #pragma unroll
        for (int t = 0; t < 4; ++t) {
            q[2 * t] = __low2float(qh0[t]);     q[2 * t + 1] = __high2float(qh0[t]);
            q[8 + 2 * t] = __low2float(qh1[t]); q[9 + 2 * t] = __high2float(qh1[t]);
        }
    }
    int p0 = g_rowptr[node], p1 = g_rowptr[node + 1];
    float s = 0.f;
    float acc[16];
    #pragma unroll
    for (int t = 0; t < 16; ++t) acc[t] = 0.f;

    int iters = (p1 - p0 + 3) >> 2;
    for (int it = 0; it < iters; ++it) {
        int p = p0 + 4 * it + sub;
        bool valid = p < p1;
        int sn = g_colsrc[valid ? p : p0];
        if (!fast) { int ts = sn >> 7; while (cnt[ts] < 3) __nanosleep(32); }
        const uint4* kp = (const uint4*)(g_qkv16 + (size_t)sn * NQKV + CCH + j * 16);
        const uint4* vp = (const uint4*)(g_qkv16 + (size_t)sn * NQKV + 2 * CCH + j * 16);
        uint4 k0 = kp[0], k1 = kp[1], v0 = vp[0], v1 = vp[1];
        const __half2* kh0 = (const __half2*)&k0; const __half2* kh1 = (const __half2*)&k1;
        const __half2* vh0 = (const __half2*)&v0; const __half2* vh1 = (const __half2*)&v1;
        float d = 0.f;
        #pragma unroll
        for (int t = 0; t < 4; ++t) {
            d += q[2 * t] * __low2float(kh0[t]) + q[2 * t + 1] * __high2float(kh0[t]);
            d += q[8 + 2 * t] * __low2float(kh1[t]) + q[9 + 2 * t] * __high2float(kh1[t]);
        }
        float e = valid ? __expf(d) : 0.f;
        s += e;
        #pragma unroll
        for (int t = 0; t < 4; ++t) {
            acc[2 * t]     = fmaf(e, __low2float(vh0[t]), acc[2 * t]);
            acc[2 * t + 1] = fmaf(e, __high2float(vh0[t]), acc[2 * t + 1]);
            acc[8 + 2 * t] = fmaf(e, __low2float(vh1[t]), acc[8 + 2 * t]);
            acc[9 + 2 * t] = fmaf(e, __high2float(vh1[t]), acc[9 + 2 * t]);
        }
    }
    s += __shfl_xor_sync(0xffffffffu, s, 8);
    s += __shfl_xor_sync(0xffffffffu, s, 16);
    #pragma unroll
    for (int t = 0; t < 16; ++t) {
        acc[t] += __shfl_xor_sync(0xffffffffu, acc[t], 8);
        acc[t] += __shfl_xor_sync(0xffffffffu, acc[t], 16);
    }
    if (sub == 0) {
        float inv = 1.f / (s + 1e-16f);
        __half2 o[8];
        #pragma unroll
        for (int t = 0; t < 8; ++t)
            o[t] = __floats2half2_rn(gelu_tanh(acc[2 * t] * inv),
                                     gelu_tanh(acc[2 * t + 1] * inv));
        uint4* dst = (uint4*)(g_agg16 + (size_t)node * CCH + j * 16);
        dst[0] = ((uint4*)o)[0];
        dst[1] = ((uint4*)o)[1];
    }
}

// ---------------- aW gemm: h = relu(beta*(gelu(agg)@aW+ab) + (1-beta)*skip) ----------------
__global__ __launch_bounds__(256, 2)
void aw_kernel(int l, const float* __restrict__ ab,
               const float* __restrict__ skipsrc, const float* __restrict__ gate) {
    extern __shared__ char sm[];
    gemm_core<128>(sm, g_agg16, g_bt + (size_t)(l * 4 + 3) * 16384, ab,
                   (l == 0) ? (float*)g_h1 : nullptr, CCH, g_a16, CCH,
                   1, skipsrc, gate, blockIdx.x * 128);
}

// ---------------- fc gemm ----------------
__global__ __launch_bounds__(256, 2)
void fc_kernel(const float* __restrict__ fcb, float* __restrict__ out) {
    extern __shared__ char sm[];
    gemm_core<64>(sm, g_a16, g_bt + (size_t)8 * 16384, fcb, out, 64,
                  nullptr, 0, 0, nullptr, nullptr, blockIdx.x * 128);
}

// ---------------- host launch ----------------
extern "C" void kernel_launch(void* const* d_in, const int* in_sizes, int n_in,
                              void* d_out, int out_size) {
    const float* x    = (const float*)d_in[0];
    const void*  ei   = d_in[1];
    const float* Wk   = (const float*)d_in[2];
    const float* bk   = (const float*)d_in[3];
    const float* Wq   = (const float*)d_in[4];
    const float* bq   = (const float*)d_in[5];
    const float* Wv   = (const float*)d_in[6];
    const float* bv   = (const float*)d_in[7];
    const float* a_rel = (const float*)d_in[8];
    const float* m_rel = (const float*)d_in[9];
    const float* p_rel = (const float*)d_in[10];
    const float* skip  = (const float*)d_in[11];
    const float* aW    = (const float*)d_in[12];
    const float* ab    = (const float*)d_in[13];
    const float* fcW   = (const float*)d_in[14];
    const float* fcb   = (const float*)d_in[15];
    float* out = (float*)d_out;

    float* p_h1;
    cudaGetSymbolAddress((void**)&p_h1, g_h1);

    cudaFuncSetAttribute(qkv_edge_kernel, cudaFuncAttributeMaxDynamicSharedMemorySize, 69632);
    cudaFuncSetAttribute(aw_kernel, cudaFuncAttributeMaxDynamicSharedMemorySize, 69632);
    cudaFuncSetAttribute(fc_kernel, cudaFuncAttributeMaxDynamicSharedMemorySize, 52224);

    // #1 prep (CSR persistent | flags | bias | cvt_x | prep_b)
    prep_all<<<PREP_BLKS, 256>>>(x, ei, Wk, bk, Wq, bq, Wv, bv,
                                 a_rel, m_rel, p_rel, aW, fcW);
    // #2 layer 0: QKV gemm + edge (flag-overlapped)
    qkv_edge_kernel<<<FUSED_BLKS, 256, 69632>>>(0);
    // #3 aW layer 0 (writes h1 fp32 + a16 fp16)
    aw_kernel<<<M_TILES, 256, 69632>>>(0, ab, x, skip);
    // #4 layer 1 fused (ncu slot)
    qkv_edge_kernel<<<FUSED_BLKS, 256, 69632>>>(1);
    // #5 aW layer 1
    aw_kernel<<<M_TILES, 256, 69632>>>(1, ab + CCH, p_h1, skip + 1);
    // #6 fc
    fc_kernel<<<M_TILES, 256, 52224>>>(fcb, out);
}

// round 10
// speedup vs baseline: 1.2650x; 1.2650x over previous
#include <cuda_runtime.h>
#include <cuda_fp16.h>
#include <math.h>
#include <stdint.h>

#define N_NODES 40000
#define N_PAD   40064          // 313 * 128
#define N_EDGES 640000
#define CCH 128
#define NQKV 384
#define M_TILES 313
#define NB_SCAN 157

// mega_prep block ranges
#define BIASB  3
#define CVTB   10016           // N_PAD*64 / 256 exact
#define PREPB  544             // 139264 / 256
#define INITB  157
#define MEGA_BLKS (BIASB + CVTB + PREPB + INITB)

// ---------------- device scratch ----------------
__device__ __half g_a16[(size_t)N_PAD * CCH];
__device__ __half g_qkv16[(size_t)N_PAD * NQKV];
__device__ __half g_agg16[(size_t)N_PAD * CCH];    // rows >= 40000 stay zero
__device__ float  g_h1[(size_t)N_NODES * CCH];
__device__ int    g_rowptr[N_NODES + 1];
__device__ int    g_colsrc[N_EDGES];
__device__ int    g_counts[N_NODES];
__device__ int    g_fill[N_NODES];
__device__ int    g_bsums[256];
__device__ float  g_bqkv[2 * NQKV];
__device__ __half g_bt[139264];
__device__ int    g_use64;

// ---------------- helpers ----------------
__device__ __forceinline__ uint32_t smem_u32(const void* p) {
    uint32_t a;
    asm("{ .reg .u64 t; cvta.to.shared.u64 t, %1; cvt.u32.u64 %0, t; }" : "=r"(a) : "l"(p));
    return a;
}
__device__ __forceinline__ void cp_async16(uint32_t dst, const void* src) {
    asm volatile("cp.async.ca.shared.global [%0], [%1], 16;" :: "r"(dst), "l"(src));
}
__device__ __forceinline__ void cp_async_wait_all() {
    asm volatile("cp.async.commit_group;");
    asm volatile("cp.async.wait_group 0;");
}
__device__ __forceinline__ int ld_idx(const void* ei, long long pos) {
    if (g_use64) return (int)((const long long*)ei)[pos];
    return ((const int*)ei)[pos];
}
__device__ __forceinline__ float gelu_tanh(float x) {
    float x3 = x * x * x;
    return 0.5f * x * (1.0f + tanhf(0.7978845608028654f * (x + 0.044715f * x3)));
}
__device__ __forceinline__ void ldsm4(uint32_t* r, uint32_t addr) {
    asm volatile("ldmatrix.sync.aligned.m8n8.x4.shared.b16 {%0,%1,%2,%3}, [%4];"
        : "=r"(r[0]), "=r"(r[1]), "=r"(r[2]), "=r"(r[3]) : "r"(addr));
}
__device__ __forceinline__ void mma16816(float* c, const uint32_t* a, uint32_t b0, uint32_t b1) {
    asm volatile("mma.sync.aligned.m16n8k16.row.col.f32.f16.f16.f32 "
        "{%0,%1,%2,%3}, {%4,%5,%6,%7}, {%8,%9}, {%0,%1,%2,%3};"
        : "+f"(c[0]), "+f"(c[1]), "+f"(c[2]), "+f"(c[3])
        : "r"(a[0]), "r"(a[1]), "r"(a[2]), "r"(a[3]), "r"(b0), "r"(b1));
}

// ---------------- mega_prep: bias | cvt_x | prep_b(direct) | init+detect ----------------
__global__ __launch_bounds__(256)
void mega_prep(const float* __restrict__ x, const void* ei,
               const float* Wk, const float* bk, const float* Wq, const float* bq,
               const float* Wv, const float* bv,
               const float* a_rel, const float* m_rel, const float* p_rel,
               const float* aW, const float* fcW) {
    int b = blockIdx.x, tid = threadIdx.x;
    if (b < BIASB) {   // fused QKV bias
        int idx = b * 256 + tid;
        if (idx < 768) {
            int l = idx / NQKV, c = idx % NQKV;
            int t = c >> 7, cc = c & 127, h = cc >> 4, eo = cc & 15;
            float bias;
            if (t == 0) bias = bq[l * 128 + cc] * p_rel[l * 8 + h] * 0.25f;
            else {
                const float* bm = (t == 1) ? bk : bv;
                const float* R  = (t == 1) ? a_rel : m_rel;
                float sb = 0.f;
                #pragma unroll
                for (int d = 0; d < 16; ++d)
                    sb += bm[l * 128 + h * 16 + d] * R[((l * 8 + h) * 16 + d) * 16 + eo];
                bias = sb;
            }
            g_bqkv[l * NQKV + c] = bias;
        }
        return;
    }
    b -= BIASB;
    if (b < CVTB) {   // x -> fp16 (+ zero padding rows)
        int i = b * 256 + tid;            // < N_PAD*64
        if (i < N_NODES * 64) {
            float2 v = ((const float2*)x)[i];
            ((__half2*)g_a16)[i] = __floats2half2_rn(v.x, v.y);
        } else {
            ((__half2*)g_a16)[i] = __floats2half2_rn(0.f, 0.f);
        }
        return;
    }
    b -= CVTB;
    if (b < PREPB) {   // direct fused weight transform -> fp16 [tile][n][k]
        int e = b * 256 + tid;            // < 139264
        float val;
        if (e < 131072) {
            int tile = e >> 14, within = e & 16383;
            int nn = within >> 7, k = within & 127;
            int l = tile >> 2, t = tile & 3;
            if (t == 0)      val = Wq[(size_t)l * 16384 + k * 128 + nn] * p_rel[l * 8 + (nn >> 4)] * 0.25f;
            else if (t == 3) val = aW[(size_t)l * 16384 + k * 128 + nn];
            else {
                const float* Wm = (t == 1) ? Wk : Wv;
                const float* R  = (t == 1) ? a_rel : m_rel;
                int h = nn >> 4, eo = nn & 15;
                float s = 0.f;
                #pragma unroll
                for (int d = 0; d < 16; ++d)
                    s += Wm[(size_t)l * 16384 + k * 128 + h * 16 + d] * R[((l * 8 + h) * 16 + d) * 16 + eo];
                val = s;
            }
        } else {
            int e2 = e - 131072;
            int nn = e2 >> 7, k = e2 & 127;
            val = fcW[k * 64 + nn];
        }
        g_bt[e] = __float2half(val);
        return;
    }
    b -= PREPB;
    {   // init counts/fill + dtype detect
        int gi = b * 256 + tid;
        if (gi < N_NODES) { g_counts[gi] = 0; g_fill[gi] = 0; }
        if (b == 0) {
            __shared__ int any;
            if (tid == 0) any = 0;
            __syncthreads();
            int v = 0;
            const int* w = (const int*)ei;
            for (int i = tid; i < 2048; i += 256) v |= w[2 * i + 1];
            if (v) atomicOr(&any, 1);
            __syncthreads();
            if (tid == 0) g_use64 = (any == 0) ? 1 : 0;
        }
    }
}

// ---------------- CSR build ----------------
__global__ void hist_kernel(const void* ei) {
    int e = blockIdx.x * blockDim.x + threadIdx.x;
    if (e < N_EDGES) atomicAdd(&g_counts[ld_idx(ei, (long long)N_EDGES + e)], 1);
}

__global__ __launch_bounds__(256) void scan1_kernel() {
    __shared__ int wtot[8], woff[8];
    int tid = threadIdx.x;
    int gi = blockIdx.x * 256 + tid;
    int v = (gi < N_NODES) ? g_counts[gi] : 0;
    int x = v;
    #pragma unroll
    for (int o = 1; o < 32; o <<= 1) {
        int t = __shfl_up_sync(0xffffffffu, x, o);
        if ((tid & 31) >= o) x += t;
    }
    if ((tid & 31) == 31) wtot[tid >> 5] = x;
    __syncthreads();
    if (tid < 8) {
        int w = wtot[tid]; int y = w;
        #pragma unroll
        for (int o = 1; o < 8; o <<= 1) {
            int t = __shfl_up_sync(0xffu, y, o);
            if (tid >= o) y += t;
        }
        woff[tid] = y - w;
        if (tid == 7) g_bsums[blockIdx.x] = y;
    }
    __syncthreads();
    if (gi < N_NODES) g_rowptr[gi] = x - v + woff[tid >> 5];
}

__global__ __launch_bounds__(256) void scan2_kernel() {
    __shared__ int wtot[8], woff[8];
    int tid = threadIdx.x;
    int v = (tid < NB_SCAN) ? g_bsums[tid] : 0;
    int x = v;
    #pragma unroll
    for (int o = 1; o < 32; o <<= 1) {
        int t = __shfl_up_sync(0xffffffffu, x, o);
        if ((tid & 31) >= o) x += t;
    }
    if ((tid & 31) == 31) wtot[tid >> 5] = x;
    __syncthreads();
    if (tid < 8) {
        int w = wtot[tid]; int y = w;
        #pragma unroll
        for (int o = 1; o < 8; o <<= 1) {
            int t = __shfl_up_sync(0xffu, y, o);
            if (tid >= o) y += t;
        }
        woff[tid] = y - w;
    }
    __syncthreads();
    if (tid < NB_SCAN) g_bsums[tid] = x - v + woff[tid >> 5];
    if (tid == 255) g_rowptr[N_NODES] = x + woff[7];
}

__global__ void scan3_kernel() {
    int gi = blockIdx.x * blockDim.x + threadIdx.x;
    if (gi < N_NODES) g_rowptr[gi] += g_bsums[blockIdx.x];
}

__global__ void scatter_kernel(const void* ei) {
    int e = blockIdx.x * blockDim.x + threadIdx.x;
    if (e < N_EDGES) {
        int d = ld_idx(ei, (long long)N_EDGES + e);
        int s = ld_idx(ei, e);
        g_colsrc[g_rowptr[d] + atomicAdd(&g_fill[d], 1)] = s;
    }
}

// ---------------- gemm core: CTA 64m x NTn, 4 warps, warp 32m x (NT/2)n ----------------
template<int NT>
__device__ __forceinline__ void gemm_core(char* sm,
    const __half* __restrict__ A16, const __half* __restrict__ btile,
    const float* __restrict__ bias,
    float* C32, int c32s, __half* C16, int c16s,
    int mode, const float* skip, const float* gate, int m0) {
    constexpr int NB2 = NT / 32;
    constexpr uint32_t BOFF = 64 * 272;
    uint32_t sbase = smem_u32(sm);
    int tid = threadIdx.x, wid = tid >> 5, lane = tid & 31;

    const __half* asrc = A16 + (size_t)m0 * 128;
    #pragma unroll
    for (int i = tid; i < 1024; i += 128) {
        int row = i >> 4, kc = i & 15;
        cp_async16(sbase + row * 272 + kc * 16, asrc + row * 128 + kc * 8);
    }
    #pragma unroll
    for (int i = tid; i < NT * 16; i += 128) {
        int row = i >> 4, kc = i & 15;
        cp_async16(sbase + BOFF + row * 272 + kc * 16, btile + row * 128 + kc * 8);
    }
    cp_async_wait_all();
    __syncthreads();

    int wm = wid & 1, wn = wid >> 1;
    uint32_t arowoff[2];
    #pragma unroll
    for (int mb = 0; mb < 2; ++mb) {
        int arow = wm * 32 + mb * 16 + (lane & 15);
        arowoff[mb] = (uint32_t)arow * 272u + (uint32_t)(lane & 16);
    }
    uint32_t browoff[NB2];
    #pragma unroll
    for (int nb2 = 0; nb2 < NB2; ++nb2) {
        int brow = wn * (NT / 2) + nb2 * 16 + (lane & 7) + ((lane & 16) >> 1);
        browoff[nb2] = (uint32_t)brow * 272u + (uint32_t)((lane & 8) << 1);
    }

    float acc[2][2 * NB2][4];
    #pragma unroll
    for (int mb = 0; mb < 2; ++mb)
        #pragma unroll
        for (int nb = 0; nb < 2 * NB2; ++nb)
            #pragma unroll
            for (int j = 0; j < 4; ++j) acc[mb][nb][j] = 0.0f;

    #pragma unroll
    for (int ks = 0; ks < 8; ++ks) {
        uint32_t kb = (uint32_t)ks * 32u;
        uint32_t a[2][4];
        ldsm4(a[0], sbase + arowoff[0] + kb);
        ldsm4(a[1], sbase + arowoff[1] + kb);
        #pragma unroll
        for (int nb2 = 0; nb2 < NB2; ++nb2) {
            uint32_t bb[4];
            ldsm4(bb, sbase + BOFF + browoff[nb2] + kb);
            mma16816(acc[0][2 * nb2],     a[0], bb[0], bb[1]);
            mma16816(acc[1][2 * nb2],     a[1], bb[0], bb[1]);
            mma16816(acc[0][2 * nb2 + 1], a[0], bb[2], bb[3]);
            mma16816(acc[1][2 * nb2 + 1], a[1], bb[2], bb[3]);
        }
    }

    float beta = 0.f, ombeta = 0.f;
    if (mode == 1) {
        float g = gate[0];
        beta = 1.f / (1.f + expf(-g));
        ombeta = 1.f - beta;
    }
    int quad = lane >> 2, qt = lane & 3;
    int n0 = wn * (NT / 2);
    #pragma unroll
    for (int mb = 0; mb < 2; ++mb)
        #pragma unroll
        for (int half = 0; half < 2; ++half) {
            int grow = m0 + wm * 32 + mb * 16 + quad + half * 8;
            #pragma unroll
            for (int nb = 0; nb < 2 * NB2; ++nb) {
                int col = n0 + nb * 8 + qt * 2;
                float v0 = acc[mb][nb][2 * half + 0] + bias[col + 0];
                float v1 = acc[mb][nb][2 * half + 1] + bias[col + 1];
                if (mode == 1) {
                    float2 sv = make_float2(0.f, 0.f);
                    if (grow < N_NODES) sv = *(const float2*)(skip + (size_t)grow * 128 + col);
                    v0 = fmaxf(beta * v0 + ombeta * sv.x, 0.f);
                    v1 = fmaxf(beta * v1 + ombeta * sv.y, 0.f);
                }
                if (C32 && grow < N_NODES) {
                    float2 o; o.x = v0; o.y = v1;
                    *(float2*)(C32 + (size_t)grow * c32s + col) = o;
                }
                if (C16)
                    *(__half2*)(C16 + (size_t)grow * c16s + col) = __floats2half2_rn(v0, v1);
            }
        }
}

// ---------------- GEMM kernels ----------------
__global__ __launch_bounds__(128, 4)
void qkv_kernel(int l) {
    extern __shared__ char sm[];
    int bx = blockIdx.x;                  // 0..2 col tile
    gemm_core<128>(sm, g_a16, g_bt + (size_t)(l * 4 + bx) * 16384,
                   g_bqkv + l * NQKV + bx * 128,
                   nullptr, 0, g_qkv16 + bx * 128, NQKV,
                   0, nullptr, nullptr, blockIdx.y * 64);
}

__global__ __launch_bounds__(128, 4)
void aw_kernel(int l, const float* __restrict__ ab,
               const float* __restrict__ skipsrc, const float* __restrict__ gate) {
    extern __shared__ char sm[];
    gemm_core<128>(sm, g_agg16, g_bt + (size_t)(l * 4 + 3) * 16384, ab,
                   (l == 0) ? (float*)g_h1 : nullptr, CCH, g_a16, CCH,
                   1, skipsrc, gate, blockIdx.y * 64);
}

__global__ __launch_bounds__(128, 4)
void fc_kernel(const float* __restrict__ fcb, float* __restrict__ out) {
    extern __shared__ char sm[];
    gemm_core<64>(sm, g_a16, g_bt + (size_t)8 * 16384, fcb, out, 64,
                  nullptr, 0, 0, nullptr, nullptr, blockIdx.y * 64);
}

// ---------------- edge kernel: 4 edges/warp-iter, 8 lanes (1 head) per edge ----------------
__global__ __launch_bounds__(256)
void edge_kernel() {
    int tid = threadIdx.x, wid = tid >> 5, lane = tid & 31;
    int node = blockIdx.x * 8 + wid;      // grid 5000 x 8 warps = 40000 exact
    int sub = lane >> 3, j = lane & 7;    // j = head index

    float q[16];
    {
        const uint4* qp = (const uint4*)(g_qkv16 + (size_t)node * NQKV + j * 16);
        uint4 q0 = qp[0], q1 = qp[1];
        const __half2* qh0 = (const __half2*)&q0;
        const __half2* qh1 = (const __half2*)&q1;
        #pragma unroll
        for (int t = 0; t < 4; ++t) {
            q[2 * t] = __low2float(qh0[t]);     q[2 * t + 1] = __high2float(qh0[t]);
            q[8 + 2 * t] = __low2float(qh1[t]); q[9 + 2 * t] = __high2float(qh1[t]);
        }
    }
    int p0 = g_rowptr[node], p1 = g_rowptr[node + 1];
    float s = 0.f;
    float acc[16];
    #pragma unroll
    for (int t = 0; t < 16; ++t) acc[t] = 0.f;

    int iters = (p1 - p0 + 3) >> 2;
    for (int it = 0; it < iters; ++it) {
        int p = p0 + 4 * it + sub;
        bool valid = p < p1;
        int sn = g_colsrc[valid ? p : p0];
        const uint4* kp = (const uint4*)(g_qkv16 + (size_t)sn * NQKV + CCH + j * 16);
        const uint4* vp = (const uint4*)(g_qkv16 + (size_t)sn * NQKV + 2 * CCH + j * 16);
        uint4 k0 = kp[0], k1 = kp[1], v0 = vp[0], v1 = vp[1];
        const __half2* kh0 = (const __half2*)&k0; const __half2* kh1 = (const __half2*)&k1;
        const __half2* vh0 = (const __half2*)&v0; const __half2* vh1 = (const __half2*)&v1;
        float d = 0.f;
        #pragma unroll
        for (int t = 0; t < 4; ++t) {
            d += q[2 * t] * __low2float(kh0[t]) + q[2 * t + 1] * __high2float(kh0[t]);
            d += q[8 + 2 * t] * __low2float(kh1[t]) + q[9 + 2 * t] * __high2float(kh1[t]);
        }
        float e = valid ? __expf(d) : 0.f;
        s += e;
        #pragma unroll
        for (int t = 0; t < 4; ++t) {
            acc[2 * t]     = fmaf(e, __low2float(vh0[t]), acc[2 * t]);
            acc[2 * t + 1] = fmaf(e, __high2float(vh0[t]), acc[2 * t + 1]);
            acc[8 + 2 * t] = fmaf(e, __low2float(vh1[t]), acc[8 + 2 * t]);
            acc[9 + 2 * t] = fmaf(e, __high2float(vh1[t]), acc[9 + 2 * t]);
        }
    }
    s += __shfl_xor_sync(0xffffffffu, s, 8);
    s += __shfl_xor_sync(0xffffffffu, s, 16);
    #pragma unroll
    for (int t = 0; t < 16; ++t) {
        acc[t] += __shfl_xor_sync(0xffffffffu, acc[t], 8);
        acc[t] += __shfl_xor_sync(0xffffffffu, acc[t], 16);
    }
    if (sub == 0) {
        float inv = 1.f / (s + 1e-16f);
        __half2 o[8];
        #pragma unroll
        for (int t = 0; t < 8; ++t)
            o[t] = __floats2half2_rn(gelu_tanh(acc[2 * t] * inv),
                                     gelu_tanh(acc[2 * t + 1] * inv));
        uint4* dst = (uint4*)(g_agg16 + (size_t)node * CCH + j * 16);
        dst[0] = ((uint4*)o)[0];
        dst[1] = ((uint4*)o)[1];
    }
}

// ---------------- host launch ----------------
#define SMEM_G128 (64 * 272 + 128 * 272)   // 52224
#define SMEM_G64  (64 * 272 + 64 * 272)    // 34816

extern "C" void kernel_launch(void* const* d_in, const int* in_sizes, int n_in,
                              void* d_out, int out_size) {
    const float* x    = (const float*)d_in[0];
    const void*  ei   = d_in[1];
    const float* Wk   = (const float*)d_in[2];
    const float* bk   = (const float*)d_in[3];
    const float* Wq   = (const float*)d_in[4];
    const float* bq   = (const float*)d_in[5];
    const float* Wv   = (const float*)d_in[6];
    const float* bv   = (const float*)d_in[7];
    const float* a_rel = (const float*)d_in[8];
    const float* m_rel = (const float*)d_in[9];
    const float* p_rel = (const float*)d_in[10];
    const float* skip  = (const float*)d_in[11];
    const float* aW    = (const float*)d_in[12];
    const float* ab    = (const float*)d_in[13];
    const float* fcW   = (const float*)d_in[14];
    const float* fcb   = (const float*)d_in[15];
    float* out = (float*)d_out;

    float* p_h1;
    cudaGetSymbolAddress((void**)&p_h1, g_h1);

    cudaFuncSetAttribute(qkv_kernel, cudaFuncAttributeMaxDynamicSharedMemorySize, SMEM_G128);
    cudaFuncSetAttribute(aw_kernel,  cudaFuncAttributeMaxDynamicSharedMemorySize, SMEM_G128);
    cudaFuncSetAttribute(fc_kernel,  cudaFuncAttributeMaxDynamicSharedMemorySize, SMEM_G64);

    // #1 mega_prep (bias | cvt_x | prep_b | init+detect), #2 hist, #3 scan1,
    // #4 QKV layer 0 (ncu slot)
    mega_prep<<<MEGA_BLKS, 256>>>(x, ei, Wk, bk, Wq, bq, Wv, bv,
                                  a_rel, m_rel, p_rel, aW, fcW);
    hist_kernel<<<(N_EDGES + 255) / 256, 256>>>(ei);
    scan1_kernel<<<NB_SCAN, 256>>>();

    qkv_kernel<<<dim3(3, 625), 128, SMEM_G128>>>(0);

    scan2_kernel<<<1, 256>>>();
    scan3_kernel<<<NB_SCAN, 256>>>();
    scatter_kernel<<<(N_EDGES + 255) / 256, 256>>>(ei);

    edge_kernel<<<5000, 256>>>();
    aw_kernel<<<dim3(1, 625), 128, SMEM_G128>>>(0, ab, x, skip);

    qkv_kernel<<<dim3(3, 625), 128, SMEM_G128>>>(1);
    edge_kernel<<<5000, 256>>>();
    aw_kernel<<<dim3(1, 625), 128, SMEM_G128>>>(1, ab + CCH, p_h1, skip + 1);

    fc_kernel<<<dim3(1, 625), 128, SMEM_G64>>>(fcb, out);
}

// round 11
// speedup vs baseline: 1.4821x; 1.1716x over previous
#include <cuda_runtime.h>
#include <cuda_fp16.h>
#include <math.h>
#include <stdint.h>

#define N_NODES 40000
#define N_PAD   40064
#define N_EDGES 640000
#define CCH 128
#define NQKV 384
#define NB_SCAN 157

// mega_prep block ranges
#define BIASB  3
#define CVTB   10016           // N_PAD*64 / 256 exact
#define PREPB  544             // 139264 / 256
#define INITB  157
#define MEGA_BLKS (BIASB + CVTB + PREPB + INITB)

// ---------------- device scratch ----------------
__device__ __half g_a16[(size_t)N_PAD * CCH];
__device__ __half g_qkv16[(size_t)N_PAD * NQKV];
__device__ __half g_agg16[(size_t)N_PAD * CCH];
__device__ float  g_h1[(size_t)N_NODES * CCH];
__device__ int    g_rowptr[N_NODES + 1];
__device__ int    g_colsrc[N_EDGES];
__device__ int    g_counts[N_NODES];
__device__ int    g_fill[N_NODES];
__device__ int    g_bsums[256];
__device__ float  g_bqkv[2 * NQKV];
__device__ __half g_bt[139264];
__device__ int    g_use64;

// ---------------- helpers ----------------
__device__ __forceinline__ uint32_t smem_u32(const void* p) {
    uint32_t a;
    asm("{ .reg .u64 t; cvta.to.shared.u64 t, %1; cvt.u32.u64 %0, t; }" : "=r"(a) : "l"(p));
    return a;
}
__device__ __forceinline__ void cp_async16(uint32_t dst, const void* src) {
    asm volatile("cp.async.ca.shared.global [%0], [%1], 16;" :: "r"(dst), "l"(src));
}
__device__ __forceinline__ void cp_async_wait_all() {
    asm volatile("cp.async.commit_group;");
    asm volatile("cp.async.wait_group 0;");
}
__device__ __forceinline__ int ld_idx(const void* ei, long long pos) {
    if (g_use64) return (int)((const long long*)ei)[pos];
    return ((const int*)ei)[pos];
}
__device__ __forceinline__ float gelu_tanh(float x) {
    float x3 = x * x * x;
    return 0.5f * x * (1.0f + tanhf(0.7978845608028654f * (x + 0.044715f * x3)));
}
__device__ __forceinline__ void ldsm4(uint32_t* r, uint32_t addr) {
    asm volatile("ldmatrix.sync.aligned.m8n8.x4.shared.b16 {%0,%1,%2,%3}, [%4];"
        : "=r"(r[0]), "=r"(r[1]), "=r"(r[2]), "=r"(r[3]) : "r"(addr));
}
__device__ __forceinline__ void mma16816(float* c, const uint32_t* a, uint32_t b0, uint32_t b1) {
    asm volatile("mma.sync.aligned.m16n8k16.row.col.f32.f16.f16.f32 "
        "{%0,%1,%2,%3}, {%4,%5,%6,%7}, {%8,%9}, {%0,%1,%2,%3};"
        : "+f"(c[0]), "+f"(c[1]), "+f"(c[2]), "+f"(c[3])
        : "r"(a[0]), "r"(a[1]), "r"(a[2]), "r"(a[3]), "r"(b0), "r"(b1));
}

// ---------------- mega_prep: bias | cvt_x | prep_b(direct) | init+detect ----------------
__global__ __launch_bounds__(256)
void mega_prep(const float* __restrict__ x, const void* ei,
               const float* Wk, const float* bk, const float* Wq, const float* bq,
               const float* Wv, const float* bv,
               const float* a_rel, const float* m_rel, const float* p_rel,
               const float* aW, const float* fcW) {
    int b = blockIdx.x, tid = threadIdx.x;
    if (b < BIASB) {
        int idx = b * 256 + tid;
        if (idx < 768) {
            int l = idx / NQKV, c = idx % NQKV;
            int t = c >> 7, cc = c & 127, h = cc >> 4, eo = cc & 15;
            float bias;
            if (t == 0) bias = bq[l * 128 + cc] * p_rel[l * 8 + h] * 0.25f;
            else {
                const float* bm = (t == 1) ? bk : bv;
                const float* R  = (t == 1) ? a_rel : m_rel;
                float sb = 0.f;
                #pragma unroll
                for (int d = 0; d < 16; ++d)
                    sb += bm[l * 128 + h * 16 + d] * R[((l * 8 + h) * 16 + d) * 16 + eo];
                bias = sb;
            }
            g_bqkv[l * NQKV + c] = bias;
        }
        return;
    }
    b -= BIASB;
    if (b < CVTB) {
        int i = b * 256 + tid;
        if (i < N_NODES * 64) {
            float2 v = ((const float2*)x)[i];
            ((__half2*)g_a16)[i] = __floats2half2_rn(v.x, v.y);
        } else {
            ((__half2*)g_a16)[i] = __floats2half2_rn(0.f, 0.f);
        }
        return;
    }
    b -= CVTB;
    if (b < PREPB) {
        int e = b * 256 + tid;
        float val;
        if (e < 131072) {
            int tile = e >> 14, within = e & 16383;
            int nn = within >> 7, k = within & 127;
            int l = tile >> 2, t = tile & 3;
            if (t == 0)      val = Wq[(size_t)l * 16384 + k * 128 + nn] * p_rel[l * 8 + (nn >> 4)] * 0.25f;
            else if (t == 3) val = aW[(size_t)l * 16384 + k * 128 + nn];
            else {
                const float* Wm = (t == 1) ? Wk : Wv;
                const float* R  = (t == 1) ? a_rel : m_rel;
                int h = nn >> 4, eo = nn & 15;
                float s = 0.f;
                #pragma unroll
                for (int d = 0; d < 16; ++d)
                    s += Wm[(size_t)l * 16384 + k * 128 + h * 16 + d] * R[((l * 8 + h) * 16 + d) * 16 + eo];
                val = s;
            }
        } else {
            int e2 = e - 131072;
            int nn = e2 >> 7, k = e2 & 127;
            val = fcW[k * 64 + nn];
        }
        g_bt[e] = __float2half(val);
        return;
    }
    b -= PREPB;
    {
        int gi = b * 256 + tid;
        if (gi < N_NODES) { g_counts[gi] = 0; g_fill[gi] = 0; }
        if (b == 0) {
            __shared__ int any;
            if (tid == 0) any = 0;
            __syncthreads();
            int v = 0;
            const int* w = (const int*)ei;
            for (int i = tid; i < 2048; i += 256) v |= w[2 * i + 1];
            if (v) atomicOr(&any, 1);
            __syncthreads();
            if (tid == 0) g_use64 = (any == 0) ? 1 : 0;
        }
    }
}

// ---------------- CSR build ----------------
__global__ void hist_kernel(const void* ei) {
    int e = blockIdx.x * blockDim.x + threadIdx.x;
    if (e < N_EDGES) atomicAdd(&g_counts[ld_idx(ei, (long long)N_EDGES + e)], 1);
}

__global__ __launch_bounds__(256) void scan1_kernel() {
    __shared__ int wtot[8], woff[8];
    int tid = threadIdx.x;
    int gi = blockIdx.x * 256 + tid;
    int v = (gi < N_NODES) ? g_counts[gi] : 0;
    int x = v;
    #pragma unroll
    for (int o = 1; o < 32; o <<= 1) {
        int t = __shfl_up_sync(0xffffffffu, x, o);
        if ((tid & 31) >= o) x += t;
    }
    if ((tid & 31) == 31) wtot[tid >> 5] = x;
    __syncthreads();
    if (tid < 8) {
        int w = wtot[tid]; int y = w;
        #pragma unroll
        for (int o = 1; o < 8; o <<= 1) {
            int t = __shfl_up_sync(0xffu, y, o);
            if (tid >= o) y += t;
        }
        woff[tid] = y - w;
        if (tid == 7) g_bsums[blockIdx.x] = y;
    }
    __syncthreads();
    if (gi < N_NODES) g_rowptr[gi] = x - v + woff[tid >> 5];
}

__global__ __launch_bounds__(256) void scan2_kernel() {
    __shared__ int wtot[8], woff[8];
    int tid = threadIdx.x;
    int v = (tid < NB_SCAN) ? g_bsums[tid] : 0;
    int x = v;
    #pragma unroll
    for (int o = 1; o < 32; o <<= 1) {
        int t = __shfl_up_sync(0xffffffffu, x, o);
        if ((tid & 31) >= o) x += t;
    }
    if ((tid & 31) == 31) wtot[tid >> 5] = x;
    __syncthreads();
    if (tid < 8) {
        int w = wtot[tid]; int y = w;
        #pragma unroll
        for (int o = 1; o < 8; o <<= 1) {
            int t = __shfl_up_sync(0xffu, y, o);
            if (tid >= o) y += t;
        }
        woff[tid] = y - w;
    }
    __syncthreads();
    if (tid < NB_SCAN) g_bsums[tid] = x - v + woff[tid >> 5];
    if (tid == 255) g_rowptr[N_NODES] = x + woff[7];
}

__global__ void scan3_kernel() {
    int gi = blockIdx.x * blockDim.x + threadIdx.x;
    if (gi < N_NODES) g_rowptr[gi] += g_bsums[blockIdx.x];
}

__global__ void scatter_kernel(const void* ei) {
    int e = blockIdx.x * blockDim.x + threadIdx.x;
    if (e < N_EDGES) {
        int d = ld_idx(ei, (long long)N_EDGES + e);
        int s = ld_idx(ei, e);
        g_colsrc[g_rowptr[d] + atomicAdd(&g_fill[d], 1)] = s;
    }
}

// ---------------- gemm core: CTA 64m x NTn, 4 warps; optional h->smem park ----------------
template<int NT>
__device__ __forceinline__ void gemm_core(char* sm,
    const __half* __restrict__ A16, const __half* __restrict__ btile,
    const float* __restrict__ bias,
    float* C32, int c32s, __half* C16, int c16s,
    int mode, const float* skip, const float* gate, int m0, int park_h) {
    constexpr int NB2 = NT / 32;
    constexpr uint32_t BOFF = 64 * 272;
    uint32_t sbase = smem_u32(sm);
    int tid = threadIdx.x, wid = tid >> 5, lane = tid & 31;

    const __half* asrc = A16 + (size_t)m0 * 128;
    #pragma unroll
    for (int i = tid; i < 1024; i += 128) {
        int row = i >> 4, kc = i & 15;
        cp_async16(sbase + row * 272 + kc * 16, asrc + row * 128 + kc * 8);
    }
    #pragma unroll
    for (int i = tid; i < NT * 16; i += 128) {
        int row = i >> 4, kc = i & 15;
        cp_async16(sbase + BOFF + row * 272 + kc * 16, btile + row * 128 + kc * 8);
    }
    cp_async_wait_all();
    __syncthreads();

    int wm = wid & 1, wn = wid >> 1;
    uint32_t arowoff[2];
    #pragma unroll
    for (int mb = 0; mb < 2; ++mb) {
        int arow = wm * 32 + mb * 16 + (lane & 15);
        arowoff[mb] = (uint32_t)arow * 272u + (uint32_t)(lane & 16);
    }
    uint32_t browoff[NB2];
    #pragma unroll
    for (int nb2 = 0; nb2 < NB2; ++nb2) {
        int brow = wn * (NT / 2) + nb2 * 16 + (lane & 7) + ((lane & 16) >> 1);
        browoff[nb2] = (uint32_t)brow * 272u + (uint32_t)((lane & 8) << 1);
    }

    float acc[2][2 * NB2][4];
    #pragma unroll
    for (int mb = 0; mb < 2; ++mb)
        #pragma unroll
        for (int nb = 0; nb < 2 * NB2; ++nb)
            #pragma unroll
            for (int j = 0; j < 4; ++j) acc[mb][nb][j] = 0.0f;

    #pragma unroll
    for (int ks = 0; ks < 8; ++ks) {
        uint32_t kb = (uint32_t)ks * 32u;
        uint32_t a[2][4];
        ldsm4(a[0], sbase + arowoff[0] + kb);
        ldsm4(a[1], sbase + arowoff[1] + kb);
        #pragma unroll
        for (int nb2 = 0; nb2 < NB2; ++nb2) {
            uint32_t bb[4];
            ldsm4(bb, sbase + BOFF + browoff[nb2] + kb);
            mma16816(acc[0][2 * nb2],     a[0], bb[0], bb[1]);
            mma16816(acc[1][2 * nb2],     a[1], bb[0], bb[1]);
            mma16816(acc[0][2 * nb2 + 1], a[0], bb[2], bb[3]);
            mma16816(acc[1][2 * nb2 + 1], a[1], bb[2], bb[3]);
        }
    }

    if (park_h) __syncthreads();   // everyone done reading A region before overwrite

    float beta = 0.f, ombeta = 0.f;
    if (mode == 1) {
        float g = gate[0];
        beta = 1.f / (1.f + expf(-g));
        ombeta = 1.f - beta;
    }
    int quad = lane >> 2, qt = lane & 3;
    int n0 = wn * (NT / 2);
    #pragma unroll
    for (int mb = 0; mb < 2; ++mb)
        #pragma unroll
        for (int half = 0; half < 2; ++half) {
            int lr = wm * 32 + mb * 16 + quad + half * 8;
            int grow = m0 + lr;
            #pragma unroll
            for (int nb = 0; nb < 2 * NB2; ++nb) {
                int col = n0 + nb * 8 + qt * 2;
                float v0 = acc[mb][nb][2 * half + 0] + bias[col + 0];
                float v1 = acc[mb][nb][2 * half + 1] + bias[col + 1];
                if (mode == 1) {
                    float2 sv = *(const float2*)(skip + (size_t)grow * 128 + col);
                    v0 = fmaxf(beta * v0 + ombeta * sv.x, 0.f);
                    v1 = fmaxf(beta * v1 + ombeta * sv.y, 0.f);
                }
                if (C32) {
                    float2 o; o.x = v0; o.y = v1;
                    *(float2*)(C32 + (size_t)grow * c32s + col) = o;
                }
                if (C16)
                    *(__half2*)(C16 + (size_t)grow * c16s + col) = __floats2half2_rn(v0, v1);
                if (park_h)
                    *(__half2*)(sm + lr * 272 + col * 2) = __floats2half2_rn(v0, v1);
            }
        }
}

// ---------------- GEMM kernels ----------------
__global__ __launch_bounds__(128, 4)
void qkv_kernel(int l) {
    extern __shared__ char sm[];
    int bx = blockIdx.x;
    gemm_core<128>(sm, g_a16, g_bt + (size_t)(l * 4 + bx) * 16384,
                   g_bqkv + l * NQKV + bx * 128,
                   nullptr, 0, g_qkv16 + bx * 128, NQKV,
                   0, nullptr, nullptr, blockIdx.y * 64, 0);
}

__global__ __launch_bounds__(128, 4)
void aw_kernel(int l, const float* __restrict__ ab,
               const float* __restrict__ skipsrc, const float* __restrict__ gate) {
    extern __shared__ char sm[];
    gemm_core<128>(sm, g_agg16, g_bt + (size_t)(l * 4 + 3) * 16384, ab,
                   (float*)g_h1, CCH, g_a16, CCH,
                   1, skipsrc, gate, blockIdx.y * 64, 0);
}

// aw layer-1 with fused fc: h parked in smem, then 64x64x128 fc GEMM in-CTA
#define FC_OFF 52224
__global__ __launch_bounds__(128, 3)
void aw_fc_kernel(const float* __restrict__ ab,
                  const float* __restrict__ skipsrc, const float* __restrict__ gate,
                  const float* __restrict__ fcb, float* __restrict__ out) {
    extern __shared__ char sm[];
    uint32_t sbase = smem_u32(sm);
    int tid = threadIdx.x, wid = tid >> 5, lane = tid & 31;
    int m0 = blockIdx.y * 64;

    // preload fc B tile (64 rows x 128k) into third region
    {
        const __half* fsrc = g_bt + (size_t)8 * 16384;
        #pragma unroll
        for (int i = tid; i < 1024; i += 128) {
            int row = i >> 4, kc = i & 15;
            cp_async16(sbase + FC_OFF + row * 272 + kc * 16, fsrc + row * 128 + kc * 8);
        }
    }
    // aW gemm; parks h fp16 into A region
    gemm_core<128>(sm, g_agg16, g_bt + (size_t)7 * 16384, ab,
                   nullptr, 0, nullptr, 0, 1, skipsrc, gate, m0, 1);
    __syncthreads();

    // fc gemm: A = parked h (sbase), B = fc tile (sbase + FC_OFF)
    int wm = wid & 1, wn = wid >> 1;
    uint32_t arowoff[2];
    #pragma unroll
    for (int mb = 0; mb < 2; ++mb) {
        int arow = wm * 32 + mb * 16 + (lane & 15);
        arowoff[mb] = (uint32_t)arow * 272u + (uint32_t)(lane & 16);
    }
    uint32_t browoff[2];
    #pragma unroll
    for (int nb2 = 0; nb2 < 2; ++nb2) {
        int brow = wn * 32 + nb2 * 16 + (lane & 7) + ((lane & 16) >> 1);
        browoff[nb2] = (uint32_t)brow * 272u + (uint32_t)((lane & 8) << 1);
    }
    float acc[2][4][4];
    #pragma unroll
    for (int mb = 0; mb < 2; ++mb)
        #pragma unroll
        for (int nb = 0; nb < 4; ++nb)
            #pragma unroll
            for (int j = 0; j < 4; ++j) acc[mb][nb][j] = 0.0f;
    #pragma unroll
    for (int ks = 0; ks < 8; ++ks) {
        uint32_t kb = (uint32_t)ks * 32u;
        uint32_t a[2][4];
        ldsm4(a[0], sbase + arowoff[0] + kb);
        ldsm4(a[1], sbase + arowoff[1] + kb);
        #pragma unroll
        for (int nb2 = 0; nb2 < 2; ++nb2) {
            uint32_t bb[4];
            ldsm4(bb, sbase + FC_OFF + browoff[nb2] + kb);
            mma16816(acc[0][2 * nb2],     a[0], bb[0], bb[1]);
            mma16816(acc[1][2 * nb2],     a[1], bb[0], bb[1]);
            mma16816(acc[0][2 * nb2 + 1], a[0], bb[2], bb[3]);
            mma16816(acc[1][2 * nb2 + 1], a[1], bb[2], bb[3]);
        }
    }
    int quad = lane >> 2, qt = lane & 3;
    int n0 = wn * 32;
    #pragma unroll
    for (int mb = 0; mb < 2; ++mb)
        #pragma unroll
        for (int half = 0; half < 2; ++half) {
            int grow = m0 + wm * 32 + mb * 16 + quad + half * 8;
            #pragma unroll
            for (int nb = 0; nb < 4; ++nb) {
                int col = n0 + nb * 8 + qt * 2;
                float2 o;
                o.x = acc[mb][nb][2 * half + 0] + fcb[col + 0];
                o.y = acc[mb][nb][2 * half + 1] + fcb[col + 1];
                *(float2*)(out + (size_t)grow * 64 + col) = o;
            }
        }
}

// ---------------- edge kernel: 2 edges/warp-iter, 16 lanes/edge, 2x pipelined ----------------
__global__ __launch_bounds__(256)
void edge_kernel() {
    int tid = threadIdx.x, wid = tid >> 5, lane = tid & 31;
    int node = blockIdx.x * 8 + wid;      // 5000 x 8 = 40000 exact
    int sub = lane >> 4, j = lane & 15;

    float q[8];
    {
        uint4 qraw = *(const uint4*)(g_qkv16 + (size_t)node * NQKV + 8 * j);
        const __half2* qh = (const __half2*)&qraw;
        #pragma unroll
        for (int t = 0; t < 4; ++t) {
            q[2 * t]     = __low2float(qh[t]);
            q[2 * t + 1] = __high2float(qh[t]);
        }
    }
    int p0 = g_rowptr[node], p1 = g_rowptr[node + 1];
    float s = 0.f;
    float acc[8];
    #pragma unroll
    for (int t = 0; t < 8; ++t) acc[t] = 0.f;

    int iters = (p1 - p0 + 1) >> 1;
    for (int it = 0; it < iters; it += 2) {
        int pA = p0 + 2 * it + sub;
        int pB = pA + 2;
        bool vA = pA < p1;
        bool vB = (it + 1 < iters) && (pB < p1);
        int snA = g_colsrc[vA ? pA : p0];
        int snB = g_colsrc[vB ? pB : p0];
        const __half* baseA = g_qkv16 + (size_t)snA * NQKV;
        const __half* baseB = g_qkv16 + (size_t)snB * NQKV;
        uint4 kA = *(const uint4*)(baseA + CCH + 8 * j);
        uint4 vA_ = *(const uint4*)(baseA + 2 * CCH + 8 * j);
        uint4 kB = *(const uint4*)(baseB + CCH + 8 * j);
        uint4 vB_ = *(const uint4*)(baseB + 2 * CCH + 8 * j);
        {
            const __half2* kh = (const __half2*)&kA;
            const __half2* vh = (const __half2*)&vA_;
            float d = 0.f;
            #pragma unroll
            for (int t = 0; t < 4; ++t)
                d += q[2 * t] * __low2float(kh[t]) + q[2 * t + 1] * __high2float(kh[t]);
            d += __shfl_xor_sync(0xffffffffu, d, 1);
            float e = vA ? __expf(d) : 0.f;
            s += e;
            #pragma unroll
            for (int t = 0; t < 4; ++t) {
                acc[2 * t]     = fmaf(e, __low2float(vh[t]), acc[2 * t]);
                acc[2 * t + 1] = fmaf(e, __high2float(vh[t]), acc[2 * t + 1]);
            }
        }
        {
            const __half2* kh = (const __half2*)&kB;
            const __half2* vh = (const __half2*)&vB_;
            float d = 0.f;
            #pragma unroll
            for (int t = 0; t < 4; ++t)
                d += q[2 * t] * __low2float(kh[t]) + q[2 * t + 1] * __high2float(kh[t]);
            d += __shfl_xor_sync(0xffffffffu, d, 1);
            float e = vB ? __expf(d) : 0.f;
            s += e;
            #pragma unroll
            for (int t = 0; t < 4; ++t) {
                acc[2 * t]     = fmaf(e, __low2float(vh[t]), acc[2 * t]);
                acc[2 * t + 1] = fmaf(e, __high2float(vh[t]), acc[2 * t + 1]);
            }
        }
    }

    s += __shfl_xor_sync(0xffffffffu, s, 16);
    #pragma unroll
    for (int t = 0; t < 8; ++t)
        acc[t] += __shfl_xor_sync(0xffffffffu, acc[t], 16);

    if (sub == 0) {
        float inv = 1.f / (s + 1e-16f);
        __half2 o[4];
        #pragma unroll
        for (int t = 0; t < 4; ++t)
            o[t] = __floats2half2_rn(gelu_tanh(acc[2 * t] * inv),
                                     gelu_tanh(acc[2 * t + 1] * inv));
        *(uint4*)(g_agg16 + (size_t)node * CCH + 8 * j) = *(uint4*)o;
    }
}

// ---------------- host launch ----------------
#define SMEM_G128 (64 * 272 + 128 * 272)       // 52224
#define SMEM_AWFC (52224 + 64 * 272)           // 69632

extern "C" void kernel_launch(void* const* d_in, const int* in_sizes, int n_in,
                              void* d_out, int out_size) {
    const float* x    = (const float*)d_in[0];
    const void*  ei   = d_in[1];
    const float* Wk   = (const float*)d_in[2];
    const float* bk   = (const float*)d_in[3];
    const float* Wq   = (const float*)d_in[4];
    const float* bq   = (const float*)d_in[5];
    const float* Wv   = (const float*)d_in[6];
    const float* bv   = (const float*)d_in[7];
    const float* a_rel = (const float*)d_in[8];
    const float* m_rel = (const float*)d_in[9];
    const float* p_rel = (const float*)d_in[10];
    const float* skip  = (const float*)d_in[11];
    const float* aW    = (const float*)d_in[12];
    const float* ab    = (const float*)d_in[13];
    const float* fcW   = (const float*)d_in[14];
    const float* fcb   = (const float*)d_in[15];
    float* out = (float*)d_out;

    float* p_h1;
    cudaGetSymbolAddress((void**)&p_h1, g_h1);

    cudaFuncSetAttribute(qkv_kernel,   cudaFuncAttributeMaxDynamicSharedMemorySize, SMEM_G128);
    cudaFuncSetAttribute(aw_kernel,    cudaFuncAttributeMaxDynamicSharedMemorySize, SMEM_G128);
    cudaFuncSetAttribute(aw_fc_kernel, cudaFuncAttributeMaxDynamicSharedMemorySize, SMEM_AWFC);

    // #1 mega_prep, #2 hist, #3 scan1, #4 QKV layer 0 (ncu slot)
    mega_prep<<<MEGA_BLKS, 256>>>(x, ei, Wk, bk, Wq, bq, Wv, bv,
                                  a_rel, m_rel, p_rel, aW, fcW);
    hist_kernel<<<(N_EDGES + 255) / 256, 256>>>(ei);
    scan1_kernel<<<NB_SCAN, 256>>>();

    qkv_kernel<<<dim3(3, 625), 128, SMEM_G128>>>(0);

    scan2_kernel<<<1, 256>>>();
    scan3_kernel<<<NB_SCAN, 256>>>();
    scatter_kernel<<<(N_EDGES + 255) / 256, 256>>>(ei);

    edge_kernel<<<5000, 256>>>();
    aw_kernel<<<dim3(1, 625), 128, SMEM_G128>>>(0, ab, x, skip);

    qkv_kernel<<<dim3(3, 625), 128, SMEM_G128>>>(1);
    edge_kernel<<<5000, 256>>>();
    aw_fc_kernel<<<dim3(1, 625), 128, SMEM_AWFC>>>(ab + CCH, p_h1, skip + 1, fcb, out);
}